// round 17
// baseline (speedup 1.0000x reference)
#include <cuda_runtime.h>
#include <cstdint>

// ---------------- problem constants ----------------
#define BATCH 256
#define HW    147456            // 384*384 px per sample
#define NB    4096              // histogram bins == 12-bit quant levels
#define QS    4095.0f           // 12-bit quant scale

// target order-statistic ranks (0-based): q*(n-1) = 14745.5 / 132709.5
#define KL 14745
#define KH 132709

// K1 geometry: 2 blocks/sample, 1024 threads, 8 px per thread-iteration
#define TPB1   1024
#define BPS1   2
#define PXB1   (HW / BPS1)            // 73728 px per block
#define ITER1  (PXB1 / (TPB1 * 8))    // 9 iterations of 8 px

// K5 geometry: 9 blocks/sample, 512 threads, 4 groups (32 px) per thread
#define TPB5   512
#define GPT    4
#define GRP_S  (HW / 8)               // 18432 8-px groups per sample
#define BPS5   (GRP_S / (TPB5 * GPT)) // 9 blocks per sample

// ---------------- device scratch (static, allocation-free, zero-init) -------
// u12-packed means: 8 px -> 3 u32 words across three SoA planes (56.6 MB total)
__device__ __align__(16) uint32_t g_p0[BATCH * GRP_S];
__device__ __align__(16) uint32_t g_p1[BATCH * GRP_S];
__device__ __align__(16) uint32_t g_p2[BATCH * GRP_S];
__device__ __align__(16) int g_hist[BATCH * NB];   // per-sample hist (cleaned by k2)
__device__ float2 g_ab[BATCH];                     // lo, inv  (q12-value units)

// ---- K1: stream x, channel-mean, quantize u12, pack to planes, hist --------
__global__ void __launch_bounds__(TPB1) k1_quant_hist(const float* __restrict__ x) {
    __shared__ int sh[NB];
    const int s     = blockIdx.x >> 1;
    const int chunk = blockIdx.x & (BPS1 - 1);
    const int t     = threadIdx.x;

    for (int i = t; i < NB; i += TPB1) sh[i] = 0;
    __syncthreads();

    const int basePx = s * HW + chunk * PXB1;
    const int baseG  = basePx >> 3;                 // 8-px group index
    const float4* __restrict__ xin = (const float4*)x;
    const float third = 1.0f / 3.0f;

#pragma unroll 3
    for (int it = 0; it < ITER1; ++it) {
        int px = basePx + it * (TPB1 * 8) + t * 8;  // multiple of 8
        int f4 = (px * 3) >> 2;                     // 6 consecutive float4s
        float4 a = __ldcs(xin + f4 + 0);
        float4 b = __ldcs(xin + f4 + 1);
        float4 c = __ldcs(xin + f4 + 2);
        float4 d = __ldcs(xin + f4 + 3);
        float4 e = __ldcs(xin + f4 + 4);
        float4 f = __ldcs(xin + f4 + 5);

        uint32_t q0 = min((uint32_t)((a.x + a.y + a.z) * third * QS + 0.5f), 4095u);
        uint32_t q1 = min((uint32_t)((a.w + b.x + b.y) * third * QS + 0.5f), 4095u);
        uint32_t q2 = min((uint32_t)((b.z + b.w + c.x) * third * QS + 0.5f), 4095u);
        uint32_t q3 = min((uint32_t)((c.y + c.z + c.w) * third * QS + 0.5f), 4095u);
        uint32_t q4 = min((uint32_t)((d.x + d.y + d.z) * third * QS + 0.5f), 4095u);
        uint32_t q5 = min((uint32_t)((d.w + e.x + e.y) * third * QS + 0.5f), 4095u);
        uint32_t q6 = min((uint32_t)((e.z + e.w + f.x) * third * QS + 0.5f), 4095u);
        uint32_t q7 = min((uint32_t)((f.y + f.z + f.w) * third * QS + 0.5f), 4095u);

        // histogram: bin == q12 value
        atomicAdd(&sh[q0], 1); atomicAdd(&sh[q1], 1);
        atomicAdd(&sh[q2], 1); atomicAdd(&sh[q3], 1);
        atomicAdd(&sh[q4], 1); atomicAdd(&sh[q5], 1);
        atomicAdd(&sh[q6], 1); atomicAdd(&sh[q7], 1);

        // pack 8 x 12-bit -> 3 u32
        uint32_t w0 = q0 | (q1 << 12) | (q2 << 24);
        uint32_t w1 = (q2 >> 8) | (q3 << 4) | (q4 << 16) | (q5 << 28);
        uint32_t w2 = (q5 >> 4) | (q6 << 8) | (q7 << 20);

        int gi = baseG + it * TPB1 + t;
        g_p0[gi] = w0;                 // default stores: retain in L2 for K5
        g_p1[gi] = w1;
        g_p2[gi] = w2;
    }
    __syncthreads();

    int* gh = &g_hist[s * NB];
    for (int i = t; i < NB; i += TPB1) {
        int v = sh[i];
        if (v) atomicAdd(&gh[i], v);   // result unused -> REDG
    }
}

// ---- k2: scan hist, interpolate quantiles within bins, self-clean ----------
__global__ void __launch_bounds__(1024) k2_scan_interp() {
    __shared__ int   s_warp[32];
    __shared__ float s_v[4];
    const int s = blockIdx.x;
    const int t = threadIdx.x;
    const int lane = t & 31;
    const int wid  = t >> 5;

    int* gh = &g_hist[s * NB];
    int4 cw = *(int4*)(gh + 4 * t);
    *(int4*)(gh + 4 * t) = make_int4(0, 0, 0, 0);   // self-clean for graph replay
    int cnt[4] = {cw.x, cw.y, cw.z, cw.w};
    int local = cnt[0] + cnt[1] + cnt[2] + cnt[3];

    int v = local;
#pragma unroll
    for (int o = 1; o < 32; o <<= 1) {
        int n = __shfl_up_sync(0xFFFFFFFFu, v, o);
        if (lane >= o) v += n;
    }
    if (lane == 31) s_warp[wid] = v;
    __syncthreads();
    if (wid == 0) {
        int wv = s_warp[lane];
#pragma unroll
        for (int o = 1; o < 32; o <<= 1) {
            int n = __shfl_up_sync(0xFFFFFFFFu, wv, o);
            if (lane >= o) wv += n;
        }
        s_warp[lane] = wv;
    }
    __syncthreads();
    int cum = (v - local) + (wid ? s_warp[wid - 1] : 0);

    // locate 4 target ranks; interpolate within bin (q12-value units, BW = 1)
    const int targets[4] = {KL, KL + 1, KH, KH + 1};
    const int base = t * 4;
#pragma unroll
    for (int i = 0; i < 4; i++) {
        int c = cnt[i];
#pragma unroll
        for (int k = 0; k < 4; k++) {
            int r = targets[k];
            if (cum <= r && r < cum + c)
                s_v[k] = (float)(base + i) + ((float)(r - cum) + 0.5f) / (float)c - 0.5f;
        }
        cum += c;
    }
    __syncthreads();

    if (t == 0) {
        float lo = 0.5f * (s_v[0] + s_v[1]);
        float hi = 0.5f * (s_v[2] + s_v[3]);
        float rng = fmaxf(hi - lo, 1e-6f * QS);
        g_ab[s] = make_float2(lo, 1.0f / rng);
    }
}

// ---- K5: unpack u12 planes (L2-hot), normalize + clip, stream out ----------
__global__ void __launch_bounds__(TPB5) k5_norm(float* __restrict__ out) {
    const int s     = blockIdx.x / BPS5;
    const int chunk = blockIdx.x % BPS5;
    const int t     = threadIdx.x;

    float2 ab = g_ab[s];
    const float lo  = ab.x;
    const float inv = ab.y;

    const int baseG = s * GRP_S + chunk * (TPB5 * GPT);
    float4* __restrict__ o4 = (float4*)out + (size_t)s * (HW / 4)
                              + (size_t)chunk * (TPB5 * GPT) * 2;

#pragma unroll
    for (int k = 0; k < GPT; k++) {
        int gi = baseG + k * TPB5 + t;
        uint32_t w0 = __ldcs(&g_p0[gi]);   // last use of planes
        uint32_t w1 = __ldcs(&g_p1[gi]);
        uint32_t w2 = __ldcs(&g_p2[gi]);

        uint32_t u0 = w0 & 0xFFFu;
        uint32_t u1 = (w0 >> 12) & 0xFFFu;
        uint32_t u2 = ((w0 >> 24) | (w1 << 8)) & 0xFFFu;
        uint32_t u3 = (w1 >> 4) & 0xFFFu;
        uint32_t u4 = (w1 >> 16) & 0xFFFu;
        uint32_t u5 = ((w1 >> 28) | (w2 << 4)) & 0xFFFu;
        uint32_t u6 = (w2 >> 8) & 0xFFFu;
        uint32_t u7 = (w2 >> 20) & 0xFFFu;

        float4 r0, r1;
        r0.x = __saturatef(((float)u0 - lo) * inv);
        r0.y = __saturatef(((float)u1 - lo) * inv);
        r0.z = __saturatef(((float)u2 - lo) * inv);
        r0.w = __saturatef(((float)u3 - lo) * inv);
        r1.x = __saturatef(((float)u4 - lo) * inv);
        r1.y = __saturatef(((float)u5 - lo) * inv);
        r1.z = __saturatef(((float)u6 - lo) * inv);
        r1.w = __saturatef(((float)u7 - lo) * inv);

        int lg = (chunk * (TPB5 * GPT) + k * TPB5 + t);  // local group (unused base math kept simple)
        float4* dst = (float4*)out + (size_t)s * (HW / 4) + (size_t)(lg) * 2;
        __stcs(dst + 0, r0);
        __stcs(dst + 1, r1);
        (void)o4;
    }
}

// ---------------- launch ----------------
extern "C" void kernel_launch(void* const* d_in, const int* in_sizes, int n_in,
                              void* d_out, int out_size) {
    const float* x = (const float*)d_in[0];
    float* out = (float*)d_out;

    k1_quant_hist<<<BATCH * BPS1, TPB1>>>(x);
    k2_scan_interp<<<BATCH, 1024>>>();
    k5_norm<<<BATCH * BPS5, TPB5>>>(out);
}